// round 16
// baseline (speedup 1.0000x reference)
#include <cuda_runtime.h>
#include <cuda_fp16.h>
#include <cstdint>

// ---------------------------------------------------------------------------
// Problem constants
// ---------------------------------------------------------------------------
#define BB   8
#define NN   4096
#define DIMK 768
#define MTOT (BB * NN)                   // 32768
#define NELEM ((size_t)MTOT * DIMK)      // 25.2M
#define WELEM (DIMK * DIMK)              // 589824
#define NK16  (DIMK / 16)                // 48 k16 steps

// ---------------------------------------------------------------------------
// Scratch (device globals; no allocation allowed)
// ---------------------------------------------------------------------------
__device__ __half g_qh[NELEM];           // q (fp16; feeds phase 0 only)
__device__ __half g_kh[NELEM];           // k (fp16; feeds phase 1 only)
__device__ float g_gq[BB * DIMK];
__device__ float g_gk[BB * DIMK];

#define ROWS_PER_BLK 32
#define BLKS_PER_BATCH (NN / ROWS_PER_BLK)   // 128
#define NPART (BB * BLKS_PER_BATCH)          // 1024
__device__ float g_part[(size_t)NPART * DIMK];

// Fragment-layout operands (uint4 = 16B per lane per k16 step)
#define AFRAG_N ((size_t)(MTOT / 16) * NK16 * 32)     // 3.15M uint4
#define BFRAG_N ((size_t)(DIMK / 16) * NK16 * 32)     // 73728 uint4
__device__ uint4 g_xa[AFRAG_N];                  // x in A-frag layout (fp16)
__device__ uint4 g_wfa[3][BFRAG_N];              // Wq / Wk / Wr B-frags
__device__ uint4 g_avf[BB * BFRAG_N];            // gk_b ⊙ Wv A-frags
__device__ uint4 g_bcf[BB * BFRAG_N];            // (Wq + Wc_b) B-frag

// ---------------------------------------------------------------------------
// mma.sync (fp16 in, fp32 accum) + L1 prefetch hint
// ---------------------------------------------------------------------------
#define MMA16816F16(d, a, b) \
    asm volatile("mma.sync.aligned.m16n8k16.row.col.f32.f16.f16.f32 " \
        "{%0,%1,%2,%3},{%4,%5,%6,%7},{%8,%9},{%0,%1,%2,%3};" \
        : "+f"((d)[0]), "+f"((d)[1]), "+f"((d)[2]), "+f"((d)[3]) \
        : "r"((a)[0]), "r"((a)[1]), "r"((a)[2]), "r"((a)[3]), \
          "r"((b)[0]), "r"((b)[1]))

#define PF_L1(p) asm volatile("prefetch.global.L1 [%0];" :: "l"(p))

__device__ __forceinline__ uint32_t pack2h(__half a, __half b) {
    return (uint32_t)__half_as_ushort(a) |
           ((uint32_t)__half_as_ushort(b) << 16);
}
__device__ __forceinline__ uint32_t pack2f(float a, float b) {
    return pack2h(__float2half_rn(a), __float2half_rn(b));
}

__device__ __forceinline__ void store2(float* C, size_t off, float a, float b) {
    *reinterpret_cast<float2*>(C + off) = make_float2(a, b);
}
__device__ __forceinline__ void store2(__half* C, size_t off, float a, float b) {
    *reinterpret_cast<__half2*>(C + off) = __floats2half2_rn(a, b);
}

// ===========================================================================
// SMEM-FREE fp16 GEMM (R12 mainloop + L1 prefetch, distance 3):
// CTA tile 128x128, 8 warps (4m x 2n), warp tile 32x64. Per k16 per warp:
// 6 LDG.128 + 6 PREFETCH.L1 + 16 HMMA; register double buffer; no smem.
// ===========================================================================
#define STEP32 32
#define BLKOFF (NK16 * 32)              // 1536

template<typename T>
__device__ __forceinline__ void gemm_frag(
    const uint4* __restrict__ Afrag,
    const uint4* __restrict__ Bfrag,
    T* __restrict__ C, int m0, int n0)
{
    const int tid  = threadIdx.x;
    const int wid  = tid >> 5;
    const int lane = tid & 31;
    const int wm = (wid & 3) * 32;
    const int wn = (wid >> 2) * 64;

    const uint4* pa = Afrag + (size_t)((m0 + wm) >> 4) * BLKOFF + lane;
    const uint4* pb = Bfrag + (size_t)((n0 + wn) >> 4) * BLKOFF + lane;

    float acc[2][8][4];
#pragma unroll
    for (int i = 0; i < 2; i++)
#pragma unroll
        for (int j = 0; j < 8; j++)
#pragma unroll
            for (int l = 0; l < 4; l++) acc[i][j][l] = 0.f;

    uint4 a0[2], a1[2];
    uint4 b0[4], b1[4];

    a0[0] = pa[0]; a0[1] = pa[BLKOFF];
    b0[0] = pb[0];          b0[1] = pb[BLKOFF];
    b0[2] = pb[2 * BLKOFF]; b0[3] = pb[3 * BLKOFF];
    pa += STEP32; pb += STEP32;

    auto step = [&](uint4 (&ac)[2], uint4 (&bc)[4],
                    uint4 (&an)[2], uint4 (&bn)[4], bool pf) {
        if (pf) {
            an[0] = pa[0]; an[1] = pa[BLKOFF];
            bn[0] = pb[0];          bn[1] = pb[BLKOFF];
            bn[2] = pb[2 * BLKOFF]; bn[3] = pb[3 * BLKOFF];
            // L1 prefetch one step beyond the in-flight loads (dist 3 from
            // compute). No registers, no scoreboard; turns the next LDG
            // round-trip (L2 ~250cyc) into an L1 hit.
            PF_L1(pa + STEP32);
            PF_L1(pa + STEP32 + BLKOFF);
            PF_L1(pb + STEP32);
            PF_L1(pb + STEP32 + BLKOFF);
            PF_L1(pb + STEP32 + 2 * BLKOFF);
            PF_L1(pb + STEP32 + 3 * BLKOFF);
            pa += STEP32; pb += STEP32;
        }
        const uint32_t* am0 = reinterpret_cast<const uint32_t*>(&ac[0]);
        const uint32_t* am1 = reinterpret_cast<const uint32_t*>(&ac[1]);
#pragma unroll
        for (int pr = 0; pr < 4; ++pr) {
            const uint32_t* bw = reinterpret_cast<const uint32_t*>(&bc[pr]);
            MMA16816F16(acc[0][2 * pr],     am0, bw);
            MMA16816F16(acc[1][2 * pr],     am1, bw);
            MMA16816F16(acc[0][2 * pr + 1], am0, bw + 2);
            MMA16816F16(acc[1][2 * pr + 1], am1, bw + 2);
        }
    };

#pragma unroll 1
    for (int s = 0; s < NK16; s += 2) {
        step(a0, b0, a1, b1, true);
        step(a1, b1, a0, b0, s + 2 < NK16);
    }

    const int g  = lane >> 2;
    const int t2 = (lane & 3) * 2;
#pragma unroll
    for (int mt = 0; mt < 2; ++mt) {
#pragma unroll
        for (int nt = 0; nt < 8; ++nt) {
            const int r0 = m0 + wm + mt * 16 + g;
            const int c0 = n0 + wn + nt * 8 + t2;
            store2(C, (size_t)r0 * DIMK + c0,       acc[mt][nt][0], acc[mt][nt][1]);
            store2(C, (size_t)(r0 + 8) * DIMK + c0, acc[mt][nt][2], acc[mt][nt][3]);
        }
    }
}

// fused q|k: grid (12, 256); halves select weight + destination (fp16 out)
__global__ __launch_bounds__(256, 2) void gemm_qk()
{
    const int bx = blockIdx.x;
    const bool sel = bx >= 6;
    gemm_frag<__half>(g_xa, sel ? g_wfa[1] : g_wfa[0], sel ? g_kh : g_qh,
                      blockIdx.y * 128, (sel ? bx - 6 : bx) * 128);
}
// out_b = x_b @ (Wq + Wc_b)^T : grid (6, 256)
__global__ __launch_bounds__(256, 2) void gemm_out(float* __restrict__ out)
{
    const int m0 = blockIdx.y * 128;
    const int b  = m0 >> 12;
    gemm_frag<float>(g_xa, g_bcf + (size_t)b * BFRAG_N, out, m0, blockIdx.x * 128);
}

// ===========================================================================
// COMPOSE fused: Wc_b = (gk_b ⊙ Wv) @ Wr; epilogue adds Wq and writes the
// result DIRECTLY in B-frag layout to g_bcf. grid (6, 6, 8).
// ===========================================================================
__global__ __launch_bounds__(256, 2) void gemm_compose(const float* __restrict__ Wq)
{
    __shared__ __half st[128][136];      // padded: conflict-free both phases

    const int b  = blockIdx.z;
    const int m0 = blockIdx.y * 128;     // i
    const int n0 = blockIdx.x * 128;     // e
    const int tid  = threadIdx.x;
    const int wid  = tid >> 5;
    const int lane = tid & 31;
    const int wm = (wid & 3) * 32;
    const int wn = (wid >> 2) * 64;

    const uint4* pa = g_avf + (size_t)b * BFRAG_N
                    + (size_t)((m0 + wm) >> 4) * BLKOFF + lane;
    const uint4* pb = g_wfa[2] + (size_t)((n0 + wn) >> 4) * BLKOFF + lane;

    float acc[2][8][4];
#pragma unroll
    for (int i = 0; i < 2; i++)
#pragma unroll
        for (int j = 0; j < 8; j++)
#pragma unroll
            for (int l = 0; l < 4; l++) acc[i][j][l] = 0.f;

    uint4 a0[2], a1[2];
    uint4 b0[4], b1[4];

    a0[0] = pa[0]; a0[1] = pa[BLKOFF];
    b0[0] = pb[0];          b0[1] = pb[BLKOFF];
    b0[2] = pb[2 * BLKOFF]; b0[3] = pb[3 * BLKOFF];
    pa += STEP32; pb += STEP32;

    auto step = [&](uint4 (&ac)[2], uint4 (&bc)[4],
                    uint4 (&an)[2], uint4 (&bn)[4], bool pf) {
        if (pf) {
            an[0] = pa[0]; an[1] = pa[BLKOFF];
            bn[0] = pb[0];          bn[1] = pb[BLKOFF];
            bn[2] = pb[2 * BLKOFF]; bn[3] = pb[3 * BLKOFF];
            PF_L1(pa + STEP32);
            PF_L1(pa + STEP32 + BLKOFF);
            PF_L1(pb + STEP32);
            PF_L1(pb + STEP32 + BLKOFF);
            PF_L1(pb + STEP32 + 2 * BLKOFF);
            PF_L1(pb + STEP32 + 3 * BLKOFF);
            pa += STEP32; pb += STEP32;
        }
        const uint32_t* am0 = reinterpret_cast<const uint32_t*>(&ac[0]);
        const uint32_t* am1 = reinterpret_cast<const uint32_t*>(&ac[1]);
#pragma unroll
        for (int pr = 0; pr < 4; ++pr) {
            const uint32_t* bw = reinterpret_cast<const uint32_t*>(&bc[pr]);
            MMA16816F16(acc[0][2 * pr],     am0, bw);
            MMA16816F16(acc[1][2 * pr],     am1, bw);
            MMA16816F16(acc[0][2 * pr + 1], am0, bw + 2);
            MMA16816F16(acc[1][2 * pr + 1], am1, bw + 2);
        }
    };

#pragma unroll 1
    for (int s = 0; s < NK16; s += 2) {
        step(a0, b0, a1, b1, true);
        step(a1, b1, a0, b0, s + 2 < NK16);
    }

    // epilogue 1: acc + Wq -> fp16 smem tile [i_loc][e_loc]
    const int g  = lane >> 2;
    const int t2 = (lane & 3) * 2;
#pragma unroll
    for (int mt = 0; mt < 2; ++mt) {
#pragma unroll
        for (int nt = 0; nt < 8; ++nt) {
            const int rl = wm + mt * 16 + g;
            const int cl = wn + nt * 8 + t2;
            const size_t wq0 = (size_t)(m0 + rl) * DIMK + n0 + cl;
            const float2 q0 = *reinterpret_cast<const float2*>(Wq + wq0);
            const float2 q1 = *reinterpret_cast<const float2*>(Wq + wq0 + 8 * DIMK);
            *reinterpret_cast<__half2*>(&st[rl][cl]) =
                __floats2half2_rn(acc[mt][nt][0] + q0.x, acc[mt][nt][1] + q0.y);
            *reinterpret_cast<__half2*>(&st[rl + 8][cl]) =
                __floats2half2_rn(acc[mt][nt][2] + q1.x, acc[mt][nt][3] + q1.y);
        }
    }
    __syncthreads();

    // epilogue 2: smem -> B-frag words (n=e rows, k=i cols)
    const int pbase = n0 >> 4;
    const int sbase = m0 >> 4;
#pragma unroll
    for (int j = 0; j < 8; ++j) {
        const int idx = wid * 8 + j;
        const int lp = idx >> 3;             // local e-pair 0..7
        const int ls = idx & 7;              // local s     0..7
        const int e = lp * 16 + g;
        const int i = ls * 16 + t2;
        const uint32_t w0 = pack2h(st[i][e],     st[i + 1][e]);
        const uint32_t w1 = pack2h(st[i + 8][e], st[i + 9][e]);
        const uint32_t w2 = pack2h(st[i][e + 8],     st[i + 1][e + 8]);
        const uint32_t w3 = pack2h(st[i + 8][e + 8], st[i + 9][e + 8]);
        g_bcf[(size_t)b * BFRAG_N
              + ((size_t)(pbase + lp) * NK16 + (sbase + ls)) * 32 + lane] =
            make_uint4(w0, w1, w2, w3);
    }
}

// ---------------------------------------------------------------------------
// Prep kernels (fragment-layout writers; dst selected in DEVICE code)
// ---------------------------------------------------------------------------
__global__ __launch_bounds__(256) void prep_xa(const float* __restrict__ x)
{
    const int mblk = blockIdx.y;
    const int s    = blockIdx.x * 8 + (threadIdx.x >> 5);
    const int lane = threadIdx.x & 31;
    const int r = mblk * 16 + (lane >> 2);
    const int c = s * 16 + (lane & 3) * 2;
    const float* xr0 = x + (size_t)r * DIMK + c;
    const float* xr1 = x + (size_t)(r + 8) * DIMK + c;
    float2 v0 = *reinterpret_cast<const float2*>(xr0);
    float2 v1 = *reinterpret_cast<const float2*>(xr1);
    float2 v2 = *reinterpret_cast<const float2*>(xr0 + 8);
    float2 v3 = *reinterpret_cast<const float2*>(xr1 + 8);
    g_xa[((size_t)mblk * NK16 + s) * 32 + lane] =
        make_uint4(pack2f(v0.x, v0.y), pack2f(v1.x, v1.y),
                   pack2f(v2.x, v2.y), pack2f(v3.x, v3.y));
}

// all three weights in one launch: grid (6, 48, 3)
__global__ __launch_bounds__(256) void prep_wf3(
    const float* __restrict__ Wq, const float* __restrict__ Wk,
    const float* __restrict__ Wr)
{
    const int slot = blockIdx.z;
    const float* W = (slot == 0) ? Wq : (slot == 1) ? Wk : Wr;
    uint4* __restrict__ dst = g_wfa[slot];
    const int p    = blockIdx.y;
    const int s    = blockIdx.x * 8 + (threadIdx.x >> 5);
    const int lane = threadIdx.x & 31;
    const int nA = p * 16 + (lane >> 2);
    const int nB = nA + 8;
    const int k0 = s * 16 + (lane & 3) * 2;
    const float* Wk0 = W + (size_t)k0 * DIMK;
    uint32_t w0 = pack2f(Wk0[nA],            Wk0[DIMK + nA]);
    uint32_t w1 = pack2f(Wk0[8 * DIMK + nA], Wk0[9 * DIMK + nA]);
    uint32_t w2 = pack2f(Wk0[nB],            Wk0[DIMK + nB]);
    uint32_t w3 = pack2f(Wk0[8 * DIMK + nB], Wk0[9 * DIMK + nB]);
    dst[((size_t)p * NK16 + s) * 32 + lane] = make_uint4(w0, w1, w2, w3);
}

// (gk_b ⊙ Wv) -> per-batch A-frag; grid (6, 48, 8)
__global__ __launch_bounds__(256) void prep_av(const float* __restrict__ Wv)
{
    const int b    = blockIdx.z;
    const int mblk = blockIdx.y;
    const int s    = blockIdx.x * 8 + (threadIdx.x >> 5);
    const int lane = threadIdx.x & 31;
    const int r = mblk * 16 + (lane >> 2);
    const int c = s * 16 + (lane & 3) * 2;
    const float* gk = g_gk + b * DIMK;
    const float s0 = gk[c], s1 = gk[c + 1], s2 = gk[c + 8], s3 = gk[c + 9];
    const float* wr0 = Wv + (size_t)r * DIMK + c;
    const float* wr1 = Wv + (size_t)(r + 8) * DIMK + c;
    float2 v0 = *reinterpret_cast<const float2*>(wr0);
    float2 v1 = *reinterpret_cast<const float2*>(wr1);
    float2 v2 = *reinterpret_cast<const float2*>(wr0 + 8);
    float2 v3 = *reinterpret_cast<const float2*>(wr1 + 8);
    g_avf[(size_t)b * BFRAG_N + ((size_t)mblk * NK16 + s) * 32 + lane] =
        make_uint4(pack2f(v0.x * s0, v0.y * s1), pack2f(v1.x * s0, v1.y * s1),
                   pack2f(v2.x * s2, v2.y * s3), pack2f(v3.x * s2, v3.y * s3));
}

// ---------------------------------------------------------------------------
// Phase kernels — no max subtraction (logits provably bounded), LOG2E folded.
// ---------------------------------------------------------------------------
#define SCALE 0.03608439182435161f   // 768^-0.5
#define LOG2E 1.4426950408889634f

__global__ __launch_bounds__(256, 2) void phase_kernel(
    const float* __restrict__ coef, int phase)
{
    __shared__ float2 s_cs[DIMK / 2];     // coef * SCALE * LOG2E pairs
    __shared__ float2 s_g[DIMK / 2];
    __shared__ float2 s_acc[8][DIMK / 2];

    const int tid  = threadIdx.x;
    const int lane = tid & 31;
    const int w    = tid >> 5;
    const int blk  = blockIdx.x;
    const int b    = blk / BLKS_PER_BATCH;
    const int r0   = b * NN + (blk % BLKS_PER_BATCH) * ROWS_PER_BLK;

    const __half* __restrict__ in = (phase == 0) ? g_qh : g_kh;

    const float CS = SCALE * LOG2E;
    for (int d = tid; d < DIMK / 2; d += 256) {
        s_cs[d] = make_float2(coef[2 * d] * CS, coef[2 * d + 1] * CS);
        s_g[d]  = (phase == 0)
            ? make_float2(1.f, 1.f)
            : make_float2(g_gq[b * DIMK + 2 * d], g_gq[b * DIMK + 2 * d + 1]);
    }
    __syncthreads();

    float acc[24];
#pragma unroll
    for (int i = 0; i < 24; i++) acc[i] = 0.f;

    for (int rr = w; rr < ROWS_PER_BLK; rr += 8) {
        const __half2* rp = reinterpret_cast<const __half2*>(
            in + (size_t)(r0 + rr) * DIMK);
        float val[24];
        float sum = 0.f;
#pragma unroll
        for (int i = 0; i < 12; i++) {
            const int dp = lane + 32 * i;
            const float2 v  = __half22float2(rp[dp]);
            const float2 gg = s_g[dp];
            const float2 cs = s_cs[dp];
            const float v0 = v.x * gg.x;
            const float v1 = v.y * gg.y;
            const float e0 = exp2f(v0 * cs.x);
            const float e1 = exp2f(v1 * cs.y);
            sum += e0 + e1;
            val[2 * i]     = v0 * e0;
            val[2 * i + 1] = v1 * e1;
        }
#pragma unroll
        for (int o = 16; o > 0; o >>= 1)
            sum += __shfl_xor_sync(0xffffffffu, sum, o);
        const float inv = 1.f / sum;
#pragma unroll
        for (int i = 0; i < 24; i++)
            acc[i] = fmaf(val[i], inv, acc[i]);
    }

#pragma unroll
    for (int i = 0; i < 12; i++)
        s_acc[w][lane + 32 * i] = make_float2(acc[2 * i], acc[2 * i + 1]);
    __syncthreads();

    float2* P = reinterpret_cast<float2*>(g_part + (size_t)blk * DIMK);
    for (int d = tid; d < DIMK / 2; d += 256) {
        float sx = 0.f, sy = 0.f;
#pragma unroll
        for (int ww = 0; ww < 8; ww++) {
            const float2 t = s_acc[ww][d];
            sx += t.x; sy += t.y;
        }
        P[d] = make_float2(sx, sy);
    }
}

// grid (8, 6), block 128
__global__ void reduce_kernel(int phase)
{
    const int b = blockIdx.x;
    const int d = blockIdx.y * 128 + threadIdx.x;
    const float* P = g_part + (size_t)b * BLKS_PER_BATCH * DIMK + d;
    float s0 = 0.f, s1 = 0.f, s2 = 0.f, s3 = 0.f;
#pragma unroll 4
    for (int i = 0; i < BLKS_PER_BATCH; i += 4) {
        s0 += P[(size_t)(i + 0) * DIMK];
        s1 += P[(size_t)(i + 1) * DIMK];
        s2 += P[(size_t)(i + 2) * DIMK];
        s3 += P[(size_t)(i + 3) * DIMK];
    }
    const float s = (s0 + s1) + (s2 + s3);
    if (phase == 0) g_gq[b * DIMK + d] = s;
    else            g_gk[b * DIMK + d] = s;
}

// ---------------------------------------------------------------------------
extern "C" void kernel_launch(void* const* d_in, const int* in_sizes, int n_in,
                              void* d_out, int out_size)
{
    const float* x     = (const float*)d_in[0];
    const float* Wq    = (const float*)d_in[1];
    const float* Wk    = (const float*)d_in[2];
    const float* Wv    = (const float*)d_in[3];
    const float* Wr    = (const float*)d_in[4];
    const float* alpha = (const float*)d_in[5];
    const float* beta  = (const float*)d_in[6];
    float* out = (float*)d_out;

    prep_wf3<<<dim3(6, 48, 3), 256>>>(Wq, Wk, Wr);
    prep_xa<<<dim3(6, 2048), 256>>>(x);
    gemm_qk<<<dim3(12, 256), 256>>>();
    phase_kernel<<<NPART, 256>>>(alpha, 0);
    reduce_kernel<<<dim3(BB, 6), 128>>>(0);
    phase_kernel<<<NPART, 256>>>(beta, 1);
    reduce_kernel<<<dim3(BB, 6), 128>>>(1);
    prep_av<<<dim3(6, 48, BB), 256>>>(Wv);
    gemm_compose<<<dim3(6, 6, BB), 256>>>(Wq);
    gemm_out<<<dim3(6, 256), 256>>>(out);
}

// round 17
// speedup vs baseline: 1.0304x; 1.0304x over previous
#include <cuda_runtime.h>
#include <cuda_fp16.h>
#include <cstdint>

// ---------------------------------------------------------------------------
// Problem constants
// ---------------------------------------------------------------------------
#define BB   8
#define NN   4096
#define DIMK 768
#define MTOT (BB * NN)                   // 32768
#define NELEM ((size_t)MTOT * DIMK)      // 25.2M
#define WELEM (DIMK * DIMK)              // 589824
#define NK16  (DIMK / 16)                // 48 k16 steps

// ---------------------------------------------------------------------------
// Scratch (device globals; no allocation allowed)
// ---------------------------------------------------------------------------
__device__ __half g_qh[NELEM];           // q (fp16; feeds phase 0 only)
__device__ __half g_kh[NELEM];           // k (fp16; feeds phase 1 only)
__device__ float g_gq[BB * DIMK];
__device__ float g_gk[BB * DIMK];

#define ROWS_PER_BLK 32
#define BLKS_PER_BATCH (NN / ROWS_PER_BLK)   // 128
#define NPART (BB * BLKS_PER_BATCH)          // 1024
__device__ float g_part[(size_t)NPART * DIMK];

// Fragment-layout operands (uint4 = 16B per lane per k16 step)
#define AFRAG_N ((size_t)(MTOT / 16) * NK16 * 32)     // 3.15M uint4
#define BFRAG_N ((size_t)(DIMK / 16) * NK16 * 32)     // 73728 uint4
__device__ uint4 g_xa[AFRAG_N];                  // x in A-frag layout (fp16)
__device__ uint4 g_wfa[3][BFRAG_N];              // Wq / Wk / Wr B-frags
__device__ uint4 g_avf[BB * BFRAG_N];            // gk_b ⊙ Wv A-frags
__device__ uint4 g_bcf[BB * BFRAG_N];            // (Wq + Wc_b) B-frag

// ---------------------------------------------------------------------------
// mma.sync (fp16 in, fp32 accum)
// ---------------------------------------------------------------------------
#define MMA16816F16(d, a, b) \
    asm volatile("mma.sync.aligned.m16n8k16.row.col.f32.f16.f16.f32 " \
        "{%0,%1,%2,%3},{%4,%5,%6,%7},{%8,%9},{%0,%1,%2,%3};" \
        : "+f"((d)[0]), "+f"((d)[1]), "+f"((d)[2]), "+f"((d)[3]) \
        : "r"((a)[0]), "r"((a)[1]), "r"((a)[2]), "r"((a)[3]), \
          "r"((b)[0]), "r"((b)[1]))

__device__ __forceinline__ uint32_t pack2h(__half a, __half b) {
    return (uint32_t)__half_as_ushort(a) |
           ((uint32_t)__half_as_ushort(b) << 16);
}
__device__ __forceinline__ uint32_t pack2f(float a, float b) {
    return pack2h(__float2half_rn(a), __float2half_rn(b));
}

__device__ __forceinline__ void store2(float* C, size_t off, float a, float b) {
    *reinterpret_cast<float2*>(C + off) = make_float2(a, b);
}
__device__ __forceinline__ void store2(__half* C, size_t off, float a, float b) {
    *reinterpret_cast<__half2*>(C + off) = __floats2half2_rn(a, b);
}

// ===========================================================================
// SMEM-FREE fp16 GEMM (R12/R15 mainloop — constrained optimum; DO NOT TOUCH):
// CTA tile 128x128, 8 warps (4m x 2n), warp tile 32x64. Per k16 per warp:
// 6 LDG.128 + 16 HMMA; register double buffer; no smem, no barriers.
// ===========================================================================
#define STEP32 32
#define BLKOFF (NK16 * 32)              // 1536

template<typename T>
__device__ __forceinline__ void gemm_frag(
    const uint4* __restrict__ Afrag,
    const uint4* __restrict__ Bfrag,
    T* __restrict__ C, int m0, int n0)
{
    const int tid  = threadIdx.x;
    const int wid  = tid >> 5;
    const int lane = tid & 31;
    const int wm = (wid & 3) * 32;
    const int wn = (wid >> 2) * 64;

    const uint4* pa = Afrag + (size_t)((m0 + wm) >> 4) * BLKOFF + lane;
    const uint4* pb = Bfrag + (size_t)((n0 + wn) >> 4) * BLKOFF + lane;

    float acc[2][8][4];
#pragma unroll
    for (int i = 0; i < 2; i++)
#pragma unroll
        for (int j = 0; j < 8; j++)
#pragma unroll
            for (int l = 0; l < 4; l++) acc[i][j][l] = 0.f;

    uint4 a0[2], a1[2];
    uint4 b0[4], b1[4];

    a0[0] = pa[0]; a0[1] = pa[BLKOFF];
    b0[0] = pb[0];          b0[1] = pb[BLKOFF];
    b0[2] = pb[2 * BLKOFF]; b0[3] = pb[3 * BLKOFF];
    pa += STEP32; pb += STEP32;

    auto step = [&](uint4 (&ac)[2], uint4 (&bc)[4],
                    uint4 (&an)[2], uint4 (&bn)[4], bool pf) {
        if (pf) {
            an[0] = pa[0]; an[1] = pa[BLKOFF];
            bn[0] = pb[0];          bn[1] = pb[BLKOFF];
            bn[2] = pb[2 * BLKOFF]; bn[3] = pb[3 * BLKOFF];
            pa += STEP32; pb += STEP32;
        }
        const uint32_t* am0 = reinterpret_cast<const uint32_t*>(&ac[0]);
        const uint32_t* am1 = reinterpret_cast<const uint32_t*>(&ac[1]);
#pragma unroll
        for (int pr = 0; pr < 4; ++pr) {
            const uint32_t* bw = reinterpret_cast<const uint32_t*>(&bc[pr]);
            MMA16816F16(acc[0][2 * pr],     am0, bw);
            MMA16816F16(acc[1][2 * pr],     am1, bw);
            MMA16816F16(acc[0][2 * pr + 1], am0, bw + 2);
            MMA16816F16(acc[1][2 * pr + 1], am1, bw + 2);
        }
    };

#pragma unroll 1
    for (int s = 0; s < NK16; s += 2) {
        step(a0, b0, a1, b1, true);
        step(a1, b1, a0, b0, s + 2 < NK16);
    }

    const int g  = lane >> 2;
    const int t2 = (lane & 3) * 2;
#pragma unroll
    for (int mt = 0; mt < 2; ++mt) {
#pragma unroll
        for (int nt = 0; nt < 8; ++nt) {
            const int r0 = m0 + wm + mt * 16 + g;
            const int c0 = n0 + wn + nt * 8 + t2;
            store2(C, (size_t)r0 * DIMK + c0,       acc[mt][nt][0], acc[mt][nt][1]);
            store2(C, (size_t)(r0 + 8) * DIMK + c0, acc[mt][nt][2], acc[mt][nt][3]);
        }
    }
}

// fused q|k: grid (12, 256); halves select weight + destination (fp16 out)
__global__ __launch_bounds__(256, 2) void gemm_qk()
{
    const int bx = blockIdx.x;
    const bool sel = bx >= 6;
    gemm_frag<__half>(g_xa, sel ? g_wfa[1] : g_wfa[0], sel ? g_kh : g_qh,
                      blockIdx.y * 128, (sel ? bx - 6 : bx) * 128);
}
// out_b = x_b @ (Wq + Wc_b)^T : grid (6, 256)
__global__ __launch_bounds__(256, 2) void gemm_out(float* __restrict__ out)
{
    const int m0 = blockIdx.y * 128;
    const int b  = m0 >> 12;
    gemm_frag<float>(g_xa, g_bcf + (size_t)b * BFRAG_N, out, m0, blockIdx.x * 128);
}

// ===========================================================================
// COMPOSE fused: Wc_b = (gk_b ⊙ Wv) @ Wr; epilogue adds Wq and writes the
// result DIRECTLY in B-frag layout to g_bcf. grid (6, 6, 8).
// ===========================================================================
__global__ __launch_bounds__(256, 2) void gemm_compose(const float* __restrict__ Wq)
{
    __shared__ __half st[128][136];      // padded: conflict-free both phases

    const int b  = blockIdx.z;
    const int m0 = blockIdx.y * 128;     // i
    const int n0 = blockIdx.x * 128;     // e
    const int tid  = threadIdx.x;
    const int wid  = tid >> 5;
    const int lane = tid & 31;
    const int wm = (wid & 3) * 32;
    const int wn = (wid >> 2) * 64;

    const uint4* pa = g_avf + (size_t)b * BFRAG_N
                    + (size_t)((m0 + wm) >> 4) * BLKOFF + lane;
    const uint4* pb = g_wfa[2] + (size_t)((n0 + wn) >> 4) * BLKOFF + lane;

    float acc[2][8][4];
#pragma unroll
    for (int i = 0; i < 2; i++)
#pragma unroll
        for (int j = 0; j < 8; j++)
#pragma unroll
            for (int l = 0; l < 4; l++) acc[i][j][l] = 0.f;

    uint4 a0[2], a1[2];
    uint4 b0[4], b1[4];

    a0[0] = pa[0]; a0[1] = pa[BLKOFF];
    b0[0] = pb[0];          b0[1] = pb[BLKOFF];
    b0[2] = pb[2 * BLKOFF]; b0[3] = pb[3 * BLKOFF];
    pa += STEP32; pb += STEP32;

    auto step = [&](uint4 (&ac)[2], uint4 (&bc)[4],
                    uint4 (&an)[2], uint4 (&bn)[4], bool pf) {
        if (pf) {
            an[0] = pa[0]; an[1] = pa[BLKOFF];
            bn[0] = pb[0];          bn[1] = pb[BLKOFF];
            bn[2] = pb[2 * BLKOFF]; bn[3] = pb[3 * BLKOFF];
            pa += STEP32; pb += STEP32;
        }
        const uint32_t* am0 = reinterpret_cast<const uint32_t*>(&ac[0]);
        const uint32_t* am1 = reinterpret_cast<const uint32_t*>(&ac[1]);
#pragma unroll
        for (int pr = 0; pr < 4; ++pr) {
            const uint32_t* bw = reinterpret_cast<const uint32_t*>(&bc[pr]);
            MMA16816F16(acc[0][2 * pr],     am0, bw);
            MMA16816F16(acc[1][2 * pr],     am1, bw);
            MMA16816F16(acc[0][2 * pr + 1], am0, bw + 2);
            MMA16816F16(acc[1][2 * pr + 1], am1, bw + 2);
        }
    };

#pragma unroll 1
    for (int s = 0; s < NK16; s += 2) {
        step(a0, b0, a1, b1, true);
        step(a1, b1, a0, b0, s + 2 < NK16);
    }

    // epilogue 1: acc + Wq -> fp16 smem tile [i_loc][e_loc]
    const int g  = lane >> 2;
    const int t2 = (lane & 3) * 2;
#pragma unroll
    for (int mt = 0; mt < 2; ++mt) {
#pragma unroll
        for (int nt = 0; nt < 8; ++nt) {
            const int rl = wm + mt * 16 + g;
            const int cl = wn + nt * 8 + t2;
            const size_t wq0 = (size_t)(m0 + rl) * DIMK + n0 + cl;
            const float2 q0 = *reinterpret_cast<const float2*>(Wq + wq0);
            const float2 q1 = *reinterpret_cast<const float2*>(Wq + wq0 + 8 * DIMK);
            *reinterpret_cast<__half2*>(&st[rl][cl]) =
                __floats2half2_rn(acc[mt][nt][0] + q0.x, acc[mt][nt][1] + q0.y);
            *reinterpret_cast<__half2*>(&st[rl + 8][cl]) =
                __floats2half2_rn(acc[mt][nt][2] + q1.x, acc[mt][nt][3] + q1.y);
        }
    }
    __syncthreads();

    // epilogue 2: smem -> B-frag words (n=e rows, k=i cols)
    const int pbase = n0 >> 4;
    const int sbase = m0 >> 4;
#pragma unroll
    for (int j = 0; j < 8; ++j) {
        const int idx = wid * 8 + j;
        const int lp = idx >> 3;             // local e-pair 0..7
        const int ls = idx & 7;              // local s     0..7
        const int e = lp * 16 + g;
        const int i = ls * 16 + t2;
        const uint32_t w0 = pack2h(st[i][e],     st[i + 1][e]);
        const uint32_t w1 = pack2h(st[i + 8][e], st[i + 9][e]);
        const uint32_t w2 = pack2h(st[i][e + 8],     st[i + 1][e + 8]);
        const uint32_t w3 = pack2h(st[i + 8][e + 8], st[i + 9][e + 8]);
        g_bcf[(size_t)b * BFRAG_N
              + ((size_t)(pbase + lp) * NK16 + (sbase + ls)) * 32 + lane] =
            make_uint4(w0, w1, w2, w3);
    }
}

// ---------------------------------------------------------------------------
// Prep kernels (fragment-layout writers; dst selected in DEVICE code)
// ---------------------------------------------------------------------------
__global__ __launch_bounds__(256) void prep_xa(const float* __restrict__ x)
{
    const int mblk = blockIdx.y;
    const int s    = blockIdx.x * 8 + (threadIdx.x >> 5);
    const int lane = threadIdx.x & 31;
    const int r = mblk * 16 + (lane >> 2);
    const int c = s * 16 + (lane & 3) * 2;
    const float* xr0 = x + (size_t)r * DIMK + c;
    const float* xr1 = x + (size_t)(r + 8) * DIMK + c;
    float2 v0 = *reinterpret_cast<const float2*>(xr0);
    float2 v1 = *reinterpret_cast<const float2*>(xr1);
    float2 v2 = *reinterpret_cast<const float2*>(xr0 + 8);
    float2 v3 = *reinterpret_cast<const float2*>(xr1 + 8);
    g_xa[((size_t)mblk * NK16 + s) * 32 + lane] =
        make_uint4(pack2f(v0.x, v0.y), pack2f(v1.x, v1.y),
                   pack2f(v2.x, v2.y), pack2f(v3.x, v3.y));
}

// all three weights in one launch: grid (6, 48, 3)
__global__ __launch_bounds__(256) void prep_wf3(
    const float* __restrict__ Wq, const float* __restrict__ Wk,
    const float* __restrict__ Wr)
{
    const int slot = blockIdx.z;
    const float* W = (slot == 0) ? Wq : (slot == 1) ? Wk : Wr;
    uint4* __restrict__ dst = g_wfa[slot];
    const int p    = blockIdx.y;
    const int s    = blockIdx.x * 8 + (threadIdx.x >> 5);
    const int lane = threadIdx.x & 31;
    const int nA = p * 16 + (lane >> 2);
    const int nB = nA + 8;
    const int k0 = s * 16 + (lane & 3) * 2;
    const float* Wk0 = W + (size_t)k0 * DIMK;
    uint32_t w0 = pack2f(Wk0[nA],            Wk0[DIMK + nA]);
    uint32_t w1 = pack2f(Wk0[8 * DIMK + nA], Wk0[9 * DIMK + nA]);
    uint32_t w2 = pack2f(Wk0[nB],            Wk0[DIMK + nB]);
    uint32_t w3 = pack2f(Wk0[8 * DIMK + nB], Wk0[9 * DIMK + nB]);
    dst[((size_t)p * NK16 + s) * 32 + lane] = make_uint4(w0, w1, w2, w3);
}

// (gk_b ⊙ Wv) -> per-batch A-frag; grid (6, 48, 8)
__global__ __launch_bounds__(256) void prep_av(const float* __restrict__ Wv)
{
    const int b    = blockIdx.z;
    const int mblk = blockIdx.y;
    const int s    = blockIdx.x * 8 + (threadIdx.x >> 5);
    const int lane = threadIdx.x & 31;
    const int r = mblk * 16 + (lane >> 2);
    const int c = s * 16 + (lane & 3) * 2;
    const float* gk = g_gk + b * DIMK;
    const float s0 = gk[c], s1 = gk[c + 1], s2 = gk[c + 8], s3 = gk[c + 9];
    const float* wr0 = Wv + (size_t)r * DIMK + c;
    const float* wr1 = Wv + (size_t)(r + 8) * DIMK + c;
    float2 v0 = *reinterpret_cast<const float2*>(wr0);
    float2 v1 = *reinterpret_cast<const float2*>(wr1);
    float2 v2 = *reinterpret_cast<const float2*>(wr0 + 8);
    float2 v3 = *reinterpret_cast<const float2*>(wr1 + 8);
    g_avf[(size_t)b * BFRAG_N + ((size_t)mblk * NK16 + s) * 32 + lane] =
        make_uint4(pack2f(v0.x * s0, v0.y * s1), pack2f(v1.x * s0, v1.y * s1),
                   pack2f(v2.x * s2, v2.y * s3), pack2f(v3.x * s2, v3.y * s3));
}

// ---------------------------------------------------------------------------
// Phase kernels — gg factored OUT of the inner loop:
//   gq[d] = gg[d] * Σ_rows( v * e * inv ),  e = exp2(v * gcs[d]),
//   gcs[d] = gg[d]*coef[d]*SCALE*LOG2E  (precomputed in smem once).
// Inner loop: 1 LDS pair fewer + 1 FMUL fewer per element vs R15.
// No max subtraction (logits provably bounded).
// ---------------------------------------------------------------------------
#define SCALE 0.03608439182435161f   // 768^-0.5
#define LOG2E 1.4426950408889634f

__global__ __launch_bounds__(256, 2) void phase_kernel(
    const float* __restrict__ coef, int phase)
{
    __shared__ float2 s_gcs[DIMK / 2];    // gg * coef * SCALE * LOG2E
    __shared__ float2 s_gg[DIMK / 2];     // gg (final scale; 1.0 in phase 0)
    __shared__ float2 s_acc[8][DIMK / 2];

    const int tid  = threadIdx.x;
    const int lane = tid & 31;
    const int w    = tid >> 5;
    const int blk  = blockIdx.x;
    const int b    = blk / BLKS_PER_BATCH;
    const int r0   = b * NN + (blk % BLKS_PER_BATCH) * ROWS_PER_BLK;

    const __half* __restrict__ in = (phase == 0) ? g_qh : g_kh;

    const float CS = SCALE * LOG2E;
    for (int d = tid; d < DIMK / 2; d += 256) {
        const float c0 = coef[2 * d] * CS, c1 = coef[2 * d + 1] * CS;
        if (phase == 0) {
            s_gcs[d] = make_float2(c0, c1);
            s_gg[d]  = make_float2(1.f, 1.f);
        } else {
            const float g0 = g_gq[b * DIMK + 2 * d];
            const float g1 = g_gq[b * DIMK + 2 * d + 1];
            s_gcs[d] = make_float2(c0 * g0, c1 * g1);
            s_gg[d]  = make_float2(g0, g1);
        }
    }
    __syncthreads();

    float acc[24];
#pragma unroll
    for (int i = 0; i < 24; i++) acc[i] = 0.f;

    for (int rr = w; rr < ROWS_PER_BLK; rr += 8) {
        const __half2* rp = reinterpret_cast<const __half2*>(
            in + (size_t)(r0 + rr) * DIMK);
        float val[24];
        float sum = 0.f;
#pragma unroll
        for (int i = 0; i < 12; i++) {
            const int dp = lane + 32 * i;
            const float2 v   = __half22float2(rp[dp]);
            const float2 gcs = s_gcs[dp];
            const float e0 = exp2f(v.x * gcs.x);
            const float e1 = exp2f(v.y * gcs.y);
            sum += e0 + e1;
            val[2 * i]     = v.x * e0;
            val[2 * i + 1] = v.y * e1;
        }
#pragma unroll
        for (int o = 16; o > 0; o >>= 1)
            sum += __shfl_xor_sync(0xffffffffu, sum, o);
        const float inv = 1.f / sum;
#pragma unroll
        for (int i = 0; i < 24; i++)
            acc[i] = fmaf(val[i], inv, acc[i]);
    }

#pragma unroll
    for (int i = 0; i < 12; i++)
        s_acc[w][lane + 32 * i] = make_float2(acc[2 * i], acc[2 * i + 1]);
    __syncthreads();

    float2* P = reinterpret_cast<float2*>(g_part + (size_t)blk * DIMK);
    for (int d = tid; d < DIMK / 2; d += 256) {
        float sx = 0.f, sy = 0.f;
#pragma unroll
        for (int ww = 0; ww < 8; ww++) {
            const float2 t = s_acc[ww][d];
            sx += t.x; sy += t.y;
        }
        const float2 gg = s_gg[d];
        P[d] = make_float2(sx * gg.x, sy * gg.y);
    }
}

// grid (8, 6), block 128
__global__ void reduce_kernel(int phase)
{
    const int b = blockIdx.x;
    const int d = blockIdx.y * 128 + threadIdx.x;
    const float* P = g_part + (size_t)b * BLKS_PER_BATCH * DIMK + d;
    float s0 = 0.f, s1 = 0.f, s2 = 0.f, s3 = 0.f;
#pragma unroll 4
    for (int i = 0; i < BLKS_PER_BATCH; i += 4) {
        s0 += P[(size_t)(i + 0) * DIMK];
        s1 += P[(size_t)(i + 1) * DIMK];
        s2 += P[(size_t)(i + 2) * DIMK];
        s3 += P[(size_t)(i + 3) * DIMK];
    }
    const float s = (s0 + s1) + (s2 + s3);
    if (phase == 0) g_gq[b * DIMK + d] = s;
    else            g_gk[b * DIMK + d] = s;
}

// ---------------------------------------------------------------------------
extern "C" void kernel_launch(void* const* d_in, const int* in_sizes, int n_in,
                              void* d_out, int out_size)
{
    const float* x     = (const float*)d_in[0];
    const float* Wq    = (const float*)d_in[1];
    const float* Wk    = (const float*)d_in[2];
    const float* Wv    = (const float*)d_in[3];
    const float* Wr    = (const float*)d_in[4];
    const float* alpha = (const float*)d_in[5];
    const float* beta  = (const float*)d_in[6];
    float* out = (float*)d_out;

    prep_wf3<<<dim3(6, 48, 3), 256>>>(Wq, Wk, Wr);
    prep_xa<<<dim3(6, 2048), 256>>>(x);
    gemm_qk<<<dim3(12, 256), 256>>>();
    phase_kernel<<<NPART, 256>>>(alpha, 0);
    reduce_kernel<<<dim3(BB, 6), 128>>>(0);
    phase_kernel<<<NPART, 256>>>(beta, 1);
    reduce_kernel<<<dim3(BB, 6), 128>>>(1);
    prep_av<<<dim3(6, 48, BB), 256>>>(Wv);
    gemm_compose<<<dim3(6, 6, BB), 256>>>(Wq);
    gemm_out<<<dim3(6, 256), 256>>>(out);
}